// round 9
// baseline (speedup 1.0000x reference)
#include <cuda_runtime.h>
#include <cuda_fp16.h>
#include <stdint.h>
#include <stddef.h>

// ---------------------------------------------------------------------------
// Problem constants
// ---------------------------------------------------------------------------
#define TOK   4096          // B*S tokens
#define DIN   4096
#define DOUT  4096
#define NE    8             // experts
#define RL    16            // lora rank
#define JD    128           // NE*RL
#define NSPLIT 8            // K-splits for k_low

// gemm1 tiling
#define TILES_X 32          // DOUT/128
#define TILES_Y 32          // TOK/128
#define NTILES  1024
#define FULL_T  888         // 3 * 296 full-K tiles
#define SPL_T   136         // leftover tiles, split in K halves

// ---------------------------------------------------------------------------
// Scratch (static device globals: allocation-free rule)
// ---------------------------------------------------------------------------
static __device__ __half g_xh  [(size_t)TOK  * DIN];   // x fp16
static __device__ __half g_wh  [(size_t)DOUT * DIN];   // base_w fp16
static __device__ __half g_lah [(size_t)JD   * DIN];   // lora_A fp16
static __device__ __half g_bch [(size_t)DOUT * JD];    // Bcat fp16
static __device__ __half g_zh  [(size_t)TOK  * JD];    // z = gs*low fp16
static __device__ float  g_lowp[NSPLIT][(size_t)TOK * JD]; // split-K partials
static __device__ float  g_gs  [(size_t)TOK  * NE];    // routing weights * SCALING
static __device__ float  g_part[(size_t)SPL_T * 128 * 128]; // split-tile partials
static __device__ int    g_flag[SPL_T];                // split-tile ready flags

// ---------------------------------------------------------------------------
// PTX helpers
// ---------------------------------------------------------------------------
__device__ __forceinline__ uint32_t smem_u32(const void* p) {
    uint32_t a;
    asm("{ .reg .u64 t; cvta.to.shared.u64 t, %1; cvt.u32.u64 %0, t; }"
        : "=r"(a) : "l"(p));
    return a;
}

__device__ __forceinline__ void ldsm_x4(uint32_t& r0, uint32_t& r1,
                                        uint32_t& r2, uint32_t& r3,
                                        uint32_t addr) {
    asm volatile("ldmatrix.sync.aligned.m8n8.x4.shared.b16 {%0,%1,%2,%3}, [%4];"
                 : "=r"(r0), "=r"(r1), "=r"(r2), "=r"(r3) : "r"(addr));
}

__device__ __forceinline__ void mma16816(float& c0, float& c1, float& c2, float& c3,
                                         uint32_t a0, uint32_t a1, uint32_t a2, uint32_t a3,
                                         uint32_t b0, uint32_t b1) {
    asm volatile(
        "mma.sync.aligned.m16n8k16.row.col.f32.f16.f16.f32 "
        "{%0,%1,%2,%3}, {%4,%5,%6,%7}, {%8,%9}, {%0,%1,%2,%3};"
        : "+f"(c0), "+f"(c1), "+f"(c2), "+f"(c3)
        : "r"(a0), "r"(a1), "r"(a2), "r"(a3), "r"(b0), "r"(b1));
}

#define CP_ASYNC16(smem, gptr)                                         \
    asm volatile("cp.async.cg.shared.global [%0], [%1], 16;"           \
                 :: "r"(smem), "l"(gptr))
#define CP_COMMIT() asm volatile("cp.async.commit_group;" ::: "memory")
#define CP_WAIT1()  asm volatile("cp.async.wait_group 1;" ::: "memory")
#define CP_WAIT0()  asm volatile("cp.async.wait_group 0;" ::: "memory")

__device__ __forceinline__ uint32_t sw128(uint32_t off) {
    return off ^ ((off >> 3) & 0x70);
}

// ---------------------------------------------------------------------------
// k_prep: gate (+x->fp16) | base_w->fp16 | lora_A->fp16 | lora_B pack
// ---------------------------------------------------------------------------
#define PREP_GATE_BLKS 256
#define PREP_CONVW_BLKS 2048
#define PREP_GRID (PREP_GATE_BLKS + PREP_CONVW_BLKS + 64)

__global__ void __launch_bounds__(256) k_prep(const float* __restrict__ x,
                                              const float* __restrict__ gw,
                                              const float4* __restrict__ bw,
                                              const float4* __restrict__ la,
                                              const float* __restrict__ lb) {
    __shared__ float4 sgw[NE * 128];      // 16 KB (gate blocks only)
    const int bid = blockIdx.x;
    const int tid = threadIdx.x;

    if (bid < PREP_GATE_BLKS) {
        // ---------------- gate + x conversion ----------------
        const int wid = tid >> 5, lane = tid & 31;
        const int t0 = bid * 16 + wid * 2;

        float acc[2][NE];
#pragma unroll
        for (int tt = 0; tt < 2; tt++)
#pragma unroll
            for (int e = 0; e < NE; e++) acc[tt][e] = 0.f;

        for (int ch = 0; ch < DIN / 512; ch++) {
#pragma unroll
            for (int i = tid; i < NE * 128; i += 256) {
                int e = i >> 7, c = i & 127;
                sgw[i] = reinterpret_cast<const float4*>(
                    gw + (size_t)e * DIN + ch * 512)[c];
            }
            __syncthreads();
#pragma unroll
            for (int tt = 0; tt < 2; tt++) {
                const float4* xr = reinterpret_cast<const float4*>(
                    x + (size_t)(t0 + tt) * DIN + ch * 512);
                __half2* xo = reinterpret_cast<__half2*>(
                    g_xh + (size_t)(t0 + tt) * DIN + ch * 512);
#pragma unroll
                for (int j0 = 0; j0 < 4; j0++) {
                    int j = lane + j0 * 32;
                    float4 v = xr[j];
                    xo[2 * j]     = __floats2half2_rn(v.x, v.y);
                    xo[2 * j + 1] = __floats2half2_rn(v.z, v.w);
#pragma unroll
                    for (int e = 0; e < NE; e++) {
                        float4 w = sgw[e * 128 + j];
                        acc[tt][e] = fmaf(v.x, w.x,
                                     fmaf(v.y, w.y,
                                     fmaf(v.z, w.z,
                                     fmaf(v.w, w.w, acc[tt][e]))));
                    }
                }
            }
            __syncthreads();
        }

#pragma unroll
        for (int tt = 0; tt < 2; tt++)
#pragma unroll
            for (int e = 0; e < NE; e++)
                for (int o = 16; o; o >>= 1)
                    acc[tt][e] += __shfl_xor_sync(0xffffffffu, acc[tt][e], o);

        if (lane == 0) {
#pragma unroll
            for (int tt = 0; tt < 2; tt++) {
                float* lg = acc[tt];
                int i1 = 0;
                for (int e = 1; e < NE; e++) if (lg[e] > lg[i1]) i1 = e;
                int i2 = (i1 == 0) ? 1 : 0;
                for (int e = 0; e < NE; e++)
                    if (e != i1 && lg[e] > lg[i2]) i2 = e;
                float e2 = expf(lg[i2] - lg[i1]);
                float inv = 1.f / (1.f + e2);
                float* o = g_gs + (size_t)(t0 + tt) * NE;
#pragma unroll
                for (int e = 0; e < NE; e++) o[e] = 0.f;
                o[i1] = 2.0f * inv;        // SCALING = 2.0 folded
                o[i2] = 2.0f * e2 * inv;
            }
        }
    } else if (bid < PREP_GATE_BLKS + PREP_CONVW_BLKS) {
        // ------- conv: base_w -> g_wh ; lora_A -> g_lah (4-way MLP) -------
        const int n4_base = (DOUT * DIN) / 4;
        const int n4_tot  = n4_base + (JD * DIN) / 4;
        const int stride  = PREP_CONVW_BLKS * 256;
        for (int i0 = (bid - PREP_GATE_BLKS) * 256 + tid; i0 < n4_tot;
             i0 += 4 * stride) {
            float4 v[4];
            bool ok[4];
#pragma unroll
            for (int u = 0; u < 4; u++) {
                int i = i0 + u * stride;
                ok[u] = (i < n4_tot);
                if (ok[u]) v[u] = (i < n4_base) ? bw[i] : la[i - n4_base];
            }
#pragma unroll
            for (int u = 0; u < 4; u++) {
                if (ok[u]) {
                    int i = i0 + u * stride;
                    __half2* o = (i < n4_base)
                        ? reinterpret_cast<__half2*>(g_wh + (size_t)i * 4)
                        : reinterpret_cast<__half2*>(g_lah + (size_t)(i - n4_base) * 4);
                    o[0] = __floats2half2_rn(v[u].x, v[u].y);
                    o[1] = __floats2half2_rn(v[u].z, v[u].w);
                }
            }
        }
    } else {
        // ---------------- conv_bc: lora_B -> Bcat fp16 ----------------
        for (int idx = (bid - PREP_GATE_BLKS - PREP_CONVW_BLKS) * 256 + tid;
             idx < NE * DOUT * RL; idx += 64 * 256) {
            int e = idx >> 16;
            int rem = idx & 0xFFFF;
            int o = rem >> 4;
            int r = rem & 15;
            g_bch[(size_t)o * JD + e * RL + r] = __float2half(lb[idx]);
        }
    }
}

// ---------------------------------------------------------------------------
// Shared GEMM tile machinery constants
// ---------------------------------------------------------------------------
#define BK 64
#define NSTAGE 3
#define T_STAGE (128 * BK * 2)   // 16 KB per operand per stage
#define B_OFF   (NSTAGE * T_STAGE)
#define SMEM_TOTAL (2 * NSTAGE * T_STAGE)   // 96 KB

// ---------------------------------------------------------------------------
// k_low: split-K GEMM  low_partial[s] = x[., s*512..] @ lora_A[., s*512..]^T
// ---------------------------------------------------------------------------
__global__ void __launch_bounds__(256, 2)
k_low() {
    extern __shared__ __align__(1024) char smem[];
    const uint32_t sbase = smem_u32(smem);

    const int tid = threadIdx.x;
    const int wid = tid >> 5, lane = tid & 31;
    const int warp_m = wid & 1;
    const int warp_n = wid >> 1;
    const int split = blockIdx.x;

    const int ld_row = tid >> 3;
    const int ld_chk = tid & 7;
    const __half* gA = g_xh + ((size_t)blockIdx.y * 128 + ld_row) * DIN +
                       split * (DIN / NSPLIT) + ld_chk * 8;
    const __half* gB = g_lah + (size_t)ld_row * DIN +
                       split * (DIN / NSPLIT) + ld_chk * 8;

    uint32_t stOff[4];
#pragma unroll
    for (int p = 0; p < 4; p++)
        stOff[p] = sw128((uint32_t)(ld_row + 32 * p) * 128 + ld_chk * 16);

    const int aRow = warp_m * 64 + (lane & 15);
    const int aColH = (lane >> 4) * 8;
    const int bRow = warp_n * 32 + (lane & 7) + ((lane >> 4) * 8);
    const int bColH = ((lane >> 3) & 1) * 8;

    float acc[4][4][4];
#pragma unroll
    for (int mi = 0; mi < 4; mi++)
#pragma unroll
        for (int ni = 0; ni < 4; ni++)
#pragma unroll
            for (int c = 0; c < 4; c++) acc[mi][ni][c] = 0.f;

    const int NK = (DIN / NSPLIT) / BK;   // 8

    auto issue = [&](int kstage) {
        const int st = kstage % NSTAGE;
        const __half* ga = gA + kstage * BK;
        const __half* gb = gB + kstage * BK;
        const uint32_t aBuf = sbase + st * T_STAGE;
        const uint32_t bBuf = sbase + B_OFF + st * T_STAGE;
#pragma unroll
        for (int p = 0; p < 4; p++) {
            CP_ASYNC16(aBuf + stOff[p], ga + (size_t)(32 * p) * DIN);
            CP_ASYNC16(bBuf + stOff[p], gb + (size_t)(32 * p) * DIN);
        }
    };

    issue(0); CP_COMMIT();
    issue(1); CP_COMMIT();

    for (int kc = 0; kc < NK; kc++) {
        CP_WAIT1();
        __syncthreads();
        if (kc + 2 < NK) issue(kc + 2);
        CP_COMMIT();

        const uint32_t aT = sbase + (kc % NSTAGE) * T_STAGE;
        const uint32_t bT = sbase + B_OFF + (kc % NSTAGE) * T_STAGE;

#pragma unroll
        for (int ks = 0; ks < BK / 16; ks++) {
            uint32_t af[4][4];
#pragma unroll
            for (int mi = 0; mi < 4; mi++) {
                uint32_t off = (uint32_t)(aRow + mi * 16) * 128 +
                               (uint32_t)(aColH + ks * 16) * 2;
                ldsm_x4(af[mi][0], af[mi][1], af[mi][2], af[mi][3],
                        aT + sw128(off));
            }
            uint32_t bf[2][4];
#pragma unroll
            for (int ni2 = 0; ni2 < 2; ni2++) {
                uint32_t off = (uint32_t)(bRow + ni2 * 16) * 128 +
                               (uint32_t)(bColH + ks * 16) * 2;
                ldsm_x4(bf[ni2][0], bf[ni2][1], bf[ni2][2], bf[ni2][3],
                        bT + sw128(off));
            }
#pragma unroll
            for (int mi = 0; mi < 4; mi++) {
#pragma unroll
                for (int ni = 0; ni < 4; ni++) {
                    uint32_t b0 = bf[ni >> 1][(ni & 1) * 2 + 0];
                    uint32_t b1 = bf[ni >> 1][(ni & 1) * 2 + 1];
                    mma16816(acc[mi][ni][0], acc[mi][ni][1],
                             acc[mi][ni][2], acc[mi][ni][3],
                             af[mi][0], af[mi][1], af[mi][2], af[mi][3],
                             b0, b1);
                }
            }
        }
    }

    float* outp = g_lowp[split];
    const int rowBase = blockIdx.y * 128 + warp_m * 64 + (lane >> 2);
    const int colBase = warp_n * 32 + (lane & 3) * 2;
#pragma unroll
    for (int mi = 0; mi < 4; mi++) {
#pragma unroll
        for (int ni = 0; ni < 4; ni++) {
            int r0 = rowBase + mi * 16;
            int c0 = colBase + ni * 8;
            float* o = outp + (size_t)r0 * JD + c0;
            o[0] = acc[mi][ni][0];
            o[1] = acc[mi][ni][1];
            o += 8 * JD;
            o[0] = acc[mi][ni][2];
            o[1] = acc[mi][ni][3];
        }
    }
}

// ---------------------------------------------------------------------------
// k_z: z = gs * sum_s lowp[s] -> fp16 ; also clears split-tile flags
// ---------------------------------------------------------------------------
__global__ void __launch_bounds__(256) k_z() {
    if (blockIdx.x == 0 && threadIdx.x < SPL_T)
        g_flag[threadIdx.x] = 0;
    int i = blockIdx.x * blockDim.x + threadIdx.x;   // half2 index
    if (i < TOK * JD / 2) {
        int t = i >> 6;
        int j = (i & 63) * 2;
        float s0 = 0.f, s1 = 0.f;
#pragma unroll
        for (int s = 0; s < NSPLIT; s++) {
            const float* p = g_lowp[s] + (size_t)t * JD + j;
            s0 += p[0];
            s1 += p[1];
        }
        float g = g_gs[(size_t)t * NE + (j >> 4)];
        reinterpret_cast<__half2*>(g_zh)[i] = __floats2half2_rn(g * s0, g * s1);
    }
}

// ---------------------------------------------------------------------------
// k_gemm1: out = x @ base_w^T + bias + z @ Bcat^T.
//   1D grid of 1160 blocks:
//     [0,888):      full-K tiles (64 chunks) + lora tail + bias store
//     [888,1024):   split s=1, tile=bid, K[0:2048] -> g_part + flag
//     [1024,1160):  split s=0, tile=bid-136, K[2048:4096] + lora tail,
//                   spin on flag, combine with g_part, + bias store
// ---------------------------------------------------------------------------
__global__ void __launch_bounds__(256, 2)
k_gemm1(const float* __restrict__ bias, float* __restrict__ out) {
    extern __shared__ __align__(1024) char smem[];
    const uint32_t sbase = smem_u32(smem);

    const int bid = blockIdx.x;
    int tile, k0, nk, role;   // role: 2=full, 1=lower-half producer, 0=finisher
    if (bid < FULL_T)            { tile = bid;          k0 = 0;  nk = 64; role = 2; }
    else if (bid < NTILES)       { tile = bid;          k0 = 0;  nk = 32; role = 1; }
    else                         { tile = bid - SPL_T;  k0 = 32; nk = 32; role = 0; }
    const int bx = tile & 31;
    const int by = tile >> 5;
    const int spl = tile - FULL_T;   // valid when role < 2

    const int tid = threadIdx.x;
    const int wid = tid >> 5, lane = tid & 31;
    const int warp_m = wid & 1;
    const int warp_n = wid >> 1;

    const int ld_row = tid >> 3;
    const int ld_chk = tid & 7;
    const __half* gA = g_xh + ((size_t)by * 128 + ld_row) * DIN + k0 * BK + ld_chk * 8;
    const __half* gB = g_wh + ((size_t)bx * 128 + ld_row) * DIN + k0 * BK + ld_chk * 8;

    uint32_t stOff[4];
#pragma unroll
    for (int p = 0; p < 4; p++)
        stOff[p] = sw128((uint32_t)(ld_row + 32 * p) * 128 + ld_chk * 16);

    const int aRow = warp_m * 64 + (lane & 15);
    const int aColH = (lane >> 4) * 8;
    const int bRow = warp_n * 32 + (lane & 7) + ((lane >> 4) * 8);
    const int bColH = ((lane >> 3) & 1) * 8;

    float acc[4][4][4];
#pragma unroll
    for (int mi = 0; mi < 4; mi++)
#pragma unroll
        for (int ni = 0; ni < 4; ni++)
#pragma unroll
            for (int c = 0; c < 4; c++) acc[mi][ni][c] = 0.f;

    auto issue = [&](int kstage) {
        const int st = kstage % NSTAGE;
        const __half* ga = gA + kstage * BK;
        const __half* gb = gB + kstage * BK;
        const uint32_t aBuf = sbase + st * T_STAGE;
        const uint32_t bBuf = sbase + B_OFF + st * T_STAGE;
#pragma unroll
        for (int p = 0; p < 4; p++) {
            CP_ASYNC16(aBuf + stOff[p], ga + (size_t)(32 * p) * DIN);
            CP_ASYNC16(bBuf + stOff[p], gb + (size_t)(32 * p) * DIN);
        }
    };

    issue(0); CP_COMMIT();
    issue(1); CP_COMMIT();

    for (int kc = 0; kc < nk; kc++) {
        CP_WAIT1();
        __syncthreads();
        if (kc + 2 < nk) issue(kc + 2);
        CP_COMMIT();

        const uint32_t aT = sbase + (kc % NSTAGE) * T_STAGE;
        const uint32_t bT = sbase + B_OFF + (kc % NSTAGE) * T_STAGE;

#pragma unroll
        for (int ks = 0; ks < BK / 16; ks++) {
            uint32_t af[4][4];
#pragma unroll
            for (int mi = 0; mi < 4; mi++) {
                uint32_t off = (uint32_t)(aRow + mi * 16) * 128 +
                               (uint32_t)(aColH + ks * 16) * 2;
                ldsm_x4(af[mi][0], af[mi][1], af[mi][2], af[mi][3],
                        aT + sw128(off));
            }
            uint32_t bf[2][4];
#pragma unroll
            for (int ni2 = 0; ni2 < 2; ni2++) {
                uint32_t off = (uint32_t)(bRow + ni2 * 16) * 128 +
                               (uint32_t)(bColH + ks * 16) * 2;
                ldsm_x4(bf[ni2][0], bf[ni2][1], bf[ni2][2], bf[ni2][3],
                        bT + sw128(off));
            }
#pragma unroll
            for (int mi = 0; mi < 4; mi++) {
#pragma unroll
                for (int ni = 0; ni < 4; ni++) {
                    uint32_t b0 = bf[ni >> 1][(ni & 1) * 2 + 0];
                    uint32_t b1 = bf[ni >> 1][(ni & 1) * 2 + 1];
                    mma16816(acc[mi][ni][0], acc[mi][ni][1],
                             acc[mi][ni][2], acc[mi][ni][3],
                             af[mi][0], af[mi][1], af[mi][2], af[mi][3],
                             b0, b1);
                }
            }
        }
    }

    // ---------------- LoRA tail (role != 1): acc += z @ Bcat^T ----------
    if (role != 1) {
        __syncthreads();   // all warps done reading stage buffers
        const __half* gZ = g_zh + ((size_t)by * 128 + ld_row) * JD + ld_chk * 8;
        const __half* gC = g_bch + ((size_t)bx * 128 + ld_row) * JD + ld_chk * 8;
#pragma unroll
        for (int kc = 0; kc < 2; kc++) {
#pragma unroll
            for (int p = 0; p < 4; p++) {
                CP_ASYNC16(sbase + kc * T_STAGE + stOff[p],
                           gZ + kc * 64 + (size_t)(32 * p) * JD);
                CP_ASYNC16(sbase + B_OFF + kc * T_STAGE + stOff[p],
                           gC + kc * 64 + (size_t)(32 * p) * JD);
            }
        }
        CP_COMMIT();
        CP_WAIT0();
        __syncthreads();

#pragma unroll
        for (int kc = 0; kc < 2; kc++) {
            const uint32_t aT = sbase + kc * T_STAGE;
            const uint32_t bT = sbase + B_OFF + kc * T_STAGE;
#pragma unroll
            for (int ks = 0; ks < 4; ks++) {
                uint32_t af[4][4];
#pragma unroll
                for (int mi = 0; mi < 4; mi++) {
                    uint32_t off = (uint32_t)(aRow + mi * 16) * 128 +
                                   (uint32_t)(aColH + ks * 16) * 2;
                    ldsm_x4(af[mi][0], af[mi][1], af[mi][2], af[mi][3],
                            aT + sw128(off));
                }
                uint32_t bf[2][4];
#pragma unroll
                for (int ni2 = 0; ni2 < 2; ni2++) {
                    uint32_t off = (uint32_t)(bRow + ni2 * 16) * 128 +
                                   (uint32_t)(bColH + ks * 16) * 2;
                    ldsm_x4(bf[ni2][0], bf[ni2][1], bf[ni2][2], bf[ni2][3],
                            bT + sw128(off));
                }
#pragma unroll
                for (int mi = 0; mi < 4; mi++) {
#pragma unroll
                    for (int ni = 0; ni < 4; ni++) {
                        uint32_t b0 = bf[ni >> 1][(ni & 1) * 2 + 0];
                        uint32_t b1 = bf[ni >> 1][(ni & 1) * 2 + 1];
                        mma16816(acc[mi][ni][0], acc[mi][ni][1],
                                 acc[mi][ni][2], acc[mi][ni][3],
                                 af[mi][0], af[mi][1], af[mi][2], af[mi][3],
                                 b0, b1);
                    }
                }
            }
        }
    }

    // ---------------- epilogue ----------------
    const int rowLoc = warp_m * 64 + (lane >> 2);
    const int colLoc = warp_n * 32 + (lane & 3) * 2;

    if (role == 1) {
        // producer: write partial, release flag
        float* p = g_part + (size_t)spl * (128 * 128);
#pragma unroll
        for (int mi = 0; mi < 4; mi++) {
#pragma unroll
            for (int ni = 0; ni < 4; ni++) {
                int r0 = rowLoc + mi * 16;
                int c0 = colLoc + ni * 8;
                float* o = p + (size_t)r0 * 128 + c0;
                o[0] = acc[mi][ni][0];
                o[1] = acc[mi][ni][1];
                o += 8 * 128;
                o[0] = acc[mi][ni][2];
                o[1] = acc[mi][ni][3];
            }
        }
        __syncthreads();
        __threadfence();
        if (tid == 0) atomicExch(&g_flag[spl], 1);
        return;
    }

    if (role == 0) {
        // finisher: wait for partner partial, fold it into acc
        if (tid == 0) {
            while (atomicAdd(&g_flag[spl], 0) == 0) { }
        }
        __syncthreads();
        __threadfence();
        const float* p = g_part + (size_t)spl * (128 * 128);
#pragma unroll
        for (int mi = 0; mi < 4; mi++) {
#pragma unroll
            for (int ni = 0; ni < 4; ni++) {
                int r0 = rowLoc + mi * 16;
                int c0 = colLoc + ni * 8;
                const float* o = p + (size_t)r0 * 128 + c0;
                acc[mi][ni][0] += o[0];
                acc[mi][ni][1] += o[1];
                o += 8 * 128;
                acc[mi][ni][2] += o[0];
                acc[mi][ni][3] += o[1];
            }
        }
    }

    // store out = acc + bias (role 2 and role 0)
    const int rowBase = by * 128 + rowLoc;
    const int colBase = bx * 128 + colLoc;
#pragma unroll
    for (int mi = 0; mi < 4; mi++) {
#pragma unroll
        for (int ni = 0; ni < 4; ni++) {
            int r0 = rowBase + mi * 16;
            int c0 = colBase + ni * 8;
            float* o = out + (size_t)r0 * DOUT + c0;
            float b0 = __ldg(bias + c0);
            float b1 = __ldg(bias + c0 + 1);
            o[0] = acc[mi][ni][0] + b0;
            o[1] = acc[mi][ni][1] + b1;
            o += 8 * DOUT;
            o[0] = acc[mi][ni][2] + b0;
            o[1] = acc[mi][ni][3] + b1;
        }
    }
}

// ---------------------------------------------------------------------------
// Launcher
// ---------------------------------------------------------------------------
extern "C" void kernel_launch(void* const* d_in, const int* in_sizes, int n_in,
                              void* d_out, int out_size) {
    const float* x      = (const float*)d_in[0];
    const float* gate_w = (const float*)d_in[1];
    const float* base_w = (const float*)d_in[2];
    const float* base_b = (const float*)d_in[3];
    const float* lora_A = (const float*)d_in[4];
    const float* lora_B = (const float*)d_in[5];
    float* out = (float*)d_out;

    cudaFuncSetAttribute(k_low,
                         cudaFuncAttributeMaxDynamicSharedMemorySize, SMEM_TOTAL);
    cudaFuncSetAttribute(k_gemm1,
                         cudaFuncAttributeMaxDynamicSharedMemorySize, SMEM_TOTAL);

    // 1. prep: gate (+x conversion) | base_w/lora_A conversion | Bcat pack
    k_prep<<<PREP_GRID, 256>>>(x, gate_w, (const float4*)base_w,
                               (const float4*)lora_A, lora_B);

    // 2. low-rank activations, split-K partials
    k_low<<<dim3(NSPLIT, TOK / 128), 256, SMEM_TOTAL>>>();

    // 3. reduce partials, apply routing weights, emit fp16 z; clear flags
    k_z<<<(TOK * JD / 2 + 255) / 256, 256>>>();

    // 4. fused: out = x@W^T + bias + z@Bcat^T  (leftover tiles K-split)
    k_gemm1<<<NTILES + SPL_T, 256, SMEM_TOTAL>>>(base_b, out);
}

// round 10
// speedup vs baseline: 1.0533x; 1.0533x over previous
#include <cuda_runtime.h>
#include <cuda_fp16.h>
#include <stdint.h>
#include <stddef.h>

// ---------------------------------------------------------------------------
// Problem constants
// ---------------------------------------------------------------------------
#define TOK   4096          // B*S tokens
#define DIN   4096
#define DOUT  4096
#define NE    8             // experts
#define RL    16            // lora rank
#define JD    128           // NE*RL
#define NSPLIT 8            // K-splits for k_low

// ---------------------------------------------------------------------------
// Scratch (static device globals: allocation-free rule)
// ---------------------------------------------------------------------------
static __device__ __half g_xh  [(size_t)TOK  * DIN];   // x fp16
static __device__ __half g_wh  [(size_t)DOUT * DIN];   // base_w fp16
static __device__ __half g_lah [(size_t)JD   * DIN];   // lora_A fp16
static __device__ __half g_bch [(size_t)DOUT * JD];    // Bcat fp16
static __device__ __half g_zh  [(size_t)TOK  * JD];    // z = gs*low fp16
static __device__ float  g_lowp[NSPLIT][(size_t)TOK * JD]; // split-K partials
static __device__ float  g_gs  [(size_t)TOK  * NE];    // routing weights * SCALING

// ---------------------------------------------------------------------------
// PTX helpers
// ---------------------------------------------------------------------------
__device__ __forceinline__ uint32_t smem_u32(const void* p) {
    uint32_t a;
    asm("{ .reg .u64 t; cvta.to.shared.u64 t, %1; cvt.u32.u64 %0, t; }"
        : "=r"(a) : "l"(p));
    return a;
}

__device__ __forceinline__ void ldsm_x4(uint32_t& r0, uint32_t& r1,
                                        uint32_t& r2, uint32_t& r3,
                                        uint32_t addr) {
    asm volatile("ldmatrix.sync.aligned.m8n8.x4.shared.b16 {%0,%1,%2,%3}, [%4];"
                 : "=r"(r0), "=r"(r1), "=r"(r2), "=r"(r3) : "r"(addr));
}

__device__ __forceinline__ void mma16816(float& c0, float& c1, float& c2, float& c3,
                                         uint32_t a0, uint32_t a1, uint32_t a2, uint32_t a3,
                                         uint32_t b0, uint32_t b1) {
    asm volatile(
        "mma.sync.aligned.m16n8k16.row.col.f32.f16.f16.f32 "
        "{%0,%1,%2,%3}, {%4,%5,%6,%7}, {%8,%9}, {%0,%1,%2,%3};"
        : "+f"(c0), "+f"(c1), "+f"(c2), "+f"(c3)
        : "r"(a0), "r"(a1), "r"(a2), "r"(a3), "r"(b0), "r"(b1));
}

#define CP_ASYNC16(smem, gptr)                                         \
    asm volatile("cp.async.cg.shared.global [%0], [%1], 16;"           \
                 :: "r"(smem), "l"(gptr))
#define CP_COMMIT() asm volatile("cp.async.commit_group;" ::: "memory")
#define CP_WAIT1()  asm volatile("cp.async.wait_group 1;" ::: "memory")
#define CP_WAIT0()  asm volatile("cp.async.wait_group 0;" ::: "memory")

__device__ __forceinline__ uint32_t sw128(uint32_t off) {
    return off ^ ((off >> 3) & 0x70);
}

// ---------------------------------------------------------------------------
// k_prep: gate (+x->fp16) | base_w->fp16 | lora_A->fp16 | lora_B pack
// ---------------------------------------------------------------------------
#define PREP_GATE_BLKS 256
#define PREP_CONVW_BLKS 2048
#define PREP_GRID (PREP_GATE_BLKS + PREP_CONVW_BLKS + 64)

__global__ void __launch_bounds__(256) k_prep(const float* __restrict__ x,
                                              const float* __restrict__ gw,
                                              const float4* __restrict__ bw,
                                              const float4* __restrict__ la,
                                              const float* __restrict__ lb) {
    __shared__ float4 sgw[NE * 128];      // 16 KB (gate blocks only)
    const int bid = blockIdx.x;
    const int tid = threadIdx.x;

    if (bid < PREP_GATE_BLKS) {
        // ---------------- gate + x conversion ----------------
        const int wid = tid >> 5, lane = tid & 31;
        const int t0 = bid * 16 + wid * 2;

        float acc[2][NE];
#pragma unroll
        for (int tt = 0; tt < 2; tt++)
#pragma unroll
            for (int e = 0; e < NE; e++) acc[tt][e] = 0.f;

        for (int ch = 0; ch < DIN / 512; ch++) {
#pragma unroll
            for (int i = tid; i < NE * 128; i += 256) {
                int e = i >> 7, c = i & 127;
                sgw[i] = reinterpret_cast<const float4*>(
                    gw + (size_t)e * DIN + ch * 512)[c];
            }
            __syncthreads();
#pragma unroll
            for (int tt = 0; tt < 2; tt++) {
                const float4* xr = reinterpret_cast<const float4*>(
                    x + (size_t)(t0 + tt) * DIN + ch * 512);
                __half2* xo = reinterpret_cast<__half2*>(
                    g_xh + (size_t)(t0 + tt) * DIN + ch * 512);
#pragma unroll
                for (int j0 = 0; j0 < 4; j0++) {
                    int j = lane + j0 * 32;
                    float4 v = xr[j];
                    xo[2 * j]     = __floats2half2_rn(v.x, v.y);
                    xo[2 * j + 1] = __floats2half2_rn(v.z, v.w);
#pragma unroll
                    for (int e = 0; e < NE; e++) {
                        float4 w = sgw[e * 128 + j];
                        acc[tt][e] = fmaf(v.x, w.x,
                                     fmaf(v.y, w.y,
                                     fmaf(v.z, w.z,
                                     fmaf(v.w, w.w, acc[tt][e]))));
                    }
                }
            }
            __syncthreads();
        }

#pragma unroll
        for (int tt = 0; tt < 2; tt++)
#pragma unroll
            for (int e = 0; e < NE; e++)
                for (int o = 16; o; o >>= 1)
                    acc[tt][e] += __shfl_xor_sync(0xffffffffu, acc[tt][e], o);

        if (lane == 0) {
#pragma unroll
            for (int tt = 0; tt < 2; tt++) {
                float* lg = acc[tt];
                int i1 = 0;
                for (int e = 1; e < NE; e++) if (lg[e] > lg[i1]) i1 = e;
                int i2 = (i1 == 0) ? 1 : 0;
                for (int e = 0; e < NE; e++)
                    if (e != i1 && lg[e] > lg[i2]) i2 = e;
                float e2 = expf(lg[i2] - lg[i1]);
                float inv = 1.f / (1.f + e2);
                float* o = g_gs + (size_t)(t0 + tt) * NE;
#pragma unroll
                for (int e = 0; e < NE; e++) o[e] = 0.f;
                o[i1] = 2.0f * inv;        // SCALING = 2.0 folded
                o[i2] = 2.0f * e2 * inv;
            }
        }
    } else if (bid < PREP_GATE_BLKS + PREP_CONVW_BLKS) {
        // ------- conv: base_w -> g_wh ; lora_A -> g_lah (4-way MLP) -------
        const int n4_base = (DOUT * DIN) / 4;
        const int n4_tot  = n4_base + (JD * DIN) / 4;
        const int stride  = PREP_CONVW_BLKS * 256;
        for (int i0 = (bid - PREP_GATE_BLKS) * 256 + tid; i0 < n4_tot;
             i0 += 4 * stride) {
            float4 v[4];
            bool ok[4];
#pragma unroll
            for (int u = 0; u < 4; u++) {
                int i = i0 + u * stride;
                ok[u] = (i < n4_tot);
                if (ok[u]) v[u] = (i < n4_base) ? bw[i] : la[i - n4_base];
            }
#pragma unroll
            for (int u = 0; u < 4; u++) {
                if (ok[u]) {
                    int i = i0 + u * stride;
                    __half2* o = (i < n4_base)
                        ? reinterpret_cast<__half2*>(g_wh + (size_t)i * 4)
                        : reinterpret_cast<__half2*>(g_lah + (size_t)(i - n4_base) * 4);
                    o[0] = __floats2half2_rn(v[u].x, v[u].y);
                    o[1] = __floats2half2_rn(v[u].z, v[u].w);
                }
            }
        }
    } else {
        // ---------------- conv_bc: lora_B -> Bcat fp16 ----------------
        for (int idx = (bid - PREP_GATE_BLKS - PREP_CONVW_BLKS) * 256 + tid;
             idx < NE * DOUT * RL; idx += 64 * 256) {
            int e = idx >> 16;
            int rem = idx & 0xFFFF;
            int o = rem >> 4;
            int r = rem & 15;
            g_bch[(size_t)o * JD + e * RL + r] = __float2half(lb[idx]);
        }
    }
}

// ---------------------------------------------------------------------------
// Shared GEMM tile machinery constants
// ---------------------------------------------------------------------------
#define BK 64
#define NSTAGE 3
#define T_STAGE (128 * BK * 2)   // 16 KB per operand per stage
#define B_OFF   (NSTAGE * T_STAGE)
#define SMEM_TOTAL (2 * NSTAGE * T_STAGE)   // 96 KB

// ---------------------------------------------------------------------------
// k_low: split-K GEMM  low_partial[s] = x[., s*512..] @ lora_A[., s*512..]^T
// ---------------------------------------------------------------------------
__global__ void __launch_bounds__(256, 2)
k_low() {
    extern __shared__ __align__(1024) char smem[];
    const uint32_t sbase = smem_u32(smem);

    const int tid = threadIdx.x;
    const int wid = tid >> 5, lane = tid & 31;
    const int warp_m = wid & 1;
    const int warp_n = wid >> 1;
    const int split = blockIdx.x;

    const int ld_row = tid >> 3;
    const int ld_chk = tid & 7;
    const __half* gA = g_xh + ((size_t)blockIdx.y * 128 + ld_row) * DIN +
                       split * (DIN / NSPLIT) + ld_chk * 8;
    const __half* gB = g_lah + (size_t)ld_row * DIN +
                       split * (DIN / NSPLIT) + ld_chk * 8;

    uint32_t stOff[4];
#pragma unroll
    for (int p = 0; p < 4; p++)
        stOff[p] = sw128((uint32_t)(ld_row + 32 * p) * 128 + ld_chk * 16);

    const int aRow = warp_m * 64 + (lane & 15);
    const int aColH = (lane >> 4) * 8;
    const int bRow = warp_n * 32 + (lane & 7) + ((lane >> 4) * 8);
    const int bColH = ((lane >> 3) & 1) * 8;

    float acc[4][4][4];
#pragma unroll
    for (int mi = 0; mi < 4; mi++)
#pragma unroll
        for (int ni = 0; ni < 4; ni++)
#pragma unroll
            for (int c = 0; c < 4; c++) acc[mi][ni][c] = 0.f;

    const int NK = (DIN / NSPLIT) / BK;   // 8

    auto issue = [&](int kstage) {
        const int st = kstage % NSTAGE;
        const __half* ga = gA + kstage * BK;
        const __half* gb = gB + kstage * BK;
        const uint32_t aBuf = sbase + st * T_STAGE;
        const uint32_t bBuf = sbase + B_OFF + st * T_STAGE;
#pragma unroll
        for (int p = 0; p < 4; p++) {
            CP_ASYNC16(aBuf + stOff[p], ga + (size_t)(32 * p) * DIN);
            CP_ASYNC16(bBuf + stOff[p], gb + (size_t)(32 * p) * DIN);
        }
    };

    issue(0); CP_COMMIT();
    issue(1); CP_COMMIT();

    for (int kc = 0; kc < NK; kc++) {
        CP_WAIT1();
        __syncthreads();
        if (kc + 2 < NK) issue(kc + 2);
        CP_COMMIT();

        const uint32_t aT = sbase + (kc % NSTAGE) * T_STAGE;
        const uint32_t bT = sbase + B_OFF + (kc % NSTAGE) * T_STAGE;

#pragma unroll
        for (int ks = 0; ks < BK / 16; ks++) {
            uint32_t af[4][4];
#pragma unroll
            for (int mi = 0; mi < 4; mi++) {
                uint32_t off = (uint32_t)(aRow + mi * 16) * 128 +
                               (uint32_t)(aColH + ks * 16) * 2;
                ldsm_x4(af[mi][0], af[mi][1], af[mi][2], af[mi][3],
                        aT + sw128(off));
            }
            uint32_t bf[2][4];
#pragma unroll
            for (int ni2 = 0; ni2 < 2; ni2++) {
                uint32_t off = (uint32_t)(bRow + ni2 * 16) * 128 +
                               (uint32_t)(bColH + ks * 16) * 2;
                ldsm_x4(bf[ni2][0], bf[ni2][1], bf[ni2][2], bf[ni2][3],
                        bT + sw128(off));
            }
#pragma unroll
            for (int mi = 0; mi < 4; mi++) {
#pragma unroll
                for (int ni = 0; ni < 4; ni++) {
                    uint32_t b0 = bf[ni >> 1][(ni & 1) * 2 + 0];
                    uint32_t b1 = bf[ni >> 1][(ni & 1) * 2 + 1];
                    mma16816(acc[mi][ni][0], acc[mi][ni][1],
                             acc[mi][ni][2], acc[mi][ni][3],
                             af[mi][0], af[mi][1], af[mi][2], af[mi][3],
                             b0, b1);
                }
            }
        }
    }

    float* outp = g_lowp[split];
    const int rowBase = blockIdx.y * 128 + warp_m * 64 + (lane >> 2);
    const int colBase = warp_n * 32 + (lane & 3) * 2;
#pragma unroll
    for (int mi = 0; mi < 4; mi++) {
#pragma unroll
        for (int ni = 0; ni < 4; ni++) {
            int r0 = rowBase + mi * 16;
            int c0 = colBase + ni * 8;
            float* o = outp + (size_t)r0 * JD + c0;
            o[0] = acc[mi][ni][0];
            o[1] = acc[mi][ni][1];
            o += 8 * JD;
            o[0] = acc[mi][ni][2];
            o[1] = acc[mi][ni][3];
        }
    }
}

// ---------------------------------------------------------------------------
// k_z: z = gs * sum_s lowp[s] -> fp16
// ---------------------------------------------------------------------------
__global__ void __launch_bounds__(256) k_z() {
    int i = blockIdx.x * blockDim.x + threadIdx.x;   // half2 index
    if (i < TOK * JD / 2) {
        int t = i >> 6;
        int j = (i & 63) * 2;
        float s0 = 0.f, s1 = 0.f;
#pragma unroll
        for (int s = 0; s < NSPLIT; s++) {
            const float* p = g_lowp[s] + (size_t)t * JD + j;
            s0 += p[0];
            s1 += p[1];
        }
        float g = g_gs[(size_t)t * NE + (j >> 4)];
        reinterpret_cast<__half2*>(g_zh)[i] = __floats2half2_rn(g * s0, g * s1);
    }
}

// ---------------------------------------------------------------------------
// k_gemm1: out = x @ base_w^T + bias + z @ Bcat^T  (R8 version, reverted)
//   128x128xBK64 tiles, 3-stage cp.async, one barrier/chunk, 2 CTAs/SM.
//   TAIL: stage buffers reused for z + Bcat (K=JD=128), 8 extra mma steps.
// ---------------------------------------------------------------------------
__global__ void __launch_bounds__(256, 2)
k_gemm1(const float* __restrict__ bias, float* __restrict__ out) {
    extern __shared__ __align__(1024) char smem[];
    const uint32_t sbase = smem_u32(smem);

    const int tid = threadIdx.x;
    const int wid = tid >> 5, lane = tid & 31;
    const int warp_m = wid & 1;
    const int warp_n = wid >> 1;

    const int ld_row = tid >> 3;
    const int ld_chk = tid & 7;
    const __half* gA = g_xh + ((size_t)blockIdx.y * 128 + ld_row) * DIN + ld_chk * 8;
    const __half* gB = g_wh + ((size_t)blockIdx.x * 128 + ld_row) * DIN + ld_chk * 8;

    uint32_t stOff[4];
#pragma unroll
    for (int p = 0; p < 4; p++)
        stOff[p] = sw128((uint32_t)(ld_row + 32 * p) * 128 + ld_chk * 16);

    const int aRow = warp_m * 64 + (lane & 15);
    const int aColH = (lane >> 4) * 8;
    const int bRow = warp_n * 32 + (lane & 7) + ((lane >> 4) * 8);
    const int bColH = ((lane >> 3) & 1) * 8;

    float acc[4][4][4];
#pragma unroll
    for (int mi = 0; mi < 4; mi++)
#pragma unroll
        for (int ni = 0; ni < 4; ni++)
#pragma unroll
            for (int c = 0; c < 4; c++) acc[mi][ni][c] = 0.f;

    const int NK = DIN / BK;

    auto issue = [&](int kstage) {
        const int st = kstage % NSTAGE;
        const __half* ga = gA + kstage * BK;
        const __half* gb = gB + kstage * BK;
        const uint32_t aBuf = sbase + st * T_STAGE;
        const uint32_t bBuf = sbase + B_OFF + st * T_STAGE;
#pragma unroll
        for (int p = 0; p < 4; p++) {
            CP_ASYNC16(aBuf + stOff[p], ga + (size_t)(32 * p) * DIN);
            CP_ASYNC16(bBuf + stOff[p], gb + (size_t)(32 * p) * DIN);
        }
    };

    issue(0); CP_COMMIT();
    issue(1); CP_COMMIT();

    for (int kc = 0; kc < NK; kc++) {
        CP_WAIT1();
        __syncthreads();
        if (kc + 2 < NK) issue(kc + 2);
        CP_COMMIT();

        const uint32_t aT = sbase + (kc % NSTAGE) * T_STAGE;
        const uint32_t bT = sbase + B_OFF + (kc % NSTAGE) * T_STAGE;

#pragma unroll
        for (int ks = 0; ks < BK / 16; ks++) {
            uint32_t af[4][4];
#pragma unroll
            for (int mi = 0; mi < 4; mi++) {
                uint32_t off = (uint32_t)(aRow + mi * 16) * 128 +
                               (uint32_t)(aColH + ks * 16) * 2;
                ldsm_x4(af[mi][0], af[mi][1], af[mi][2], af[mi][3],
                        aT + sw128(off));
            }
            uint32_t bf[2][4];
#pragma unroll
            for (int ni2 = 0; ni2 < 2; ni2++) {
                uint32_t off = (uint32_t)(bRow + ni2 * 16) * 128 +
                               (uint32_t)(bColH + ks * 16) * 2;
                ldsm_x4(bf[ni2][0], bf[ni2][1], bf[ni2][2], bf[ni2][3],
                        bT + sw128(off));
            }
#pragma unroll
            for (int mi = 0; mi < 4; mi++) {
#pragma unroll
                for (int ni = 0; ni < 4; ni++) {
                    uint32_t b0 = bf[ni >> 1][(ni & 1) * 2 + 0];
                    uint32_t b1 = bf[ni >> 1][(ni & 1) * 2 + 1];
                    mma16816(acc[mi][ni][0], acc[mi][ni][1],
                             acc[mi][ni][2], acc[mi][ni][3],
                             af[mi][0], af[mi][1], af[mi][2], af[mi][3],
                             b0, b1);
                }
            }
        }
    }

    // ---------------- LoRA tail: acc += z @ Bcat^T (K = JD = 128) ----------
    __syncthreads();   // all warps done reading stage buffers
    {
        const __half* gZ = g_zh + ((size_t)blockIdx.y * 128 + ld_row) * JD + ld_chk * 8;
        const __half* gC = g_bch + ((size_t)blockIdx.x * 128 + ld_row) * JD + ld_chk * 8;
#pragma unroll
        for (int kc = 0; kc < 2; kc++) {
#pragma unroll
            for (int p = 0; p < 4; p++) {
                CP_ASYNC16(sbase + kc * T_STAGE + stOff[p],
                           gZ + kc * 64 + (size_t)(32 * p) * JD);
                CP_ASYNC16(sbase + B_OFF + kc * T_STAGE + stOff[p],
                           gC + kc * 64 + (size_t)(32 * p) * JD);
            }
        }
        CP_COMMIT();
        CP_WAIT0();
        __syncthreads();

#pragma unroll
        for (int kc = 0; kc < 2; kc++) {
            const uint32_t aT = sbase + kc * T_STAGE;
            const uint32_t bT = sbase + B_OFF + kc * T_STAGE;
#pragma unroll
            for (int ks = 0; ks < 4; ks++) {
                uint32_t af[4][4];
#pragma unroll
                for (int mi = 0; mi < 4; mi++) {
                    uint32_t off = (uint32_t)(aRow + mi * 16) * 128 +
                                   (uint32_t)(aColH + ks * 16) * 2;
                    ldsm_x4(af[mi][0], af[mi][1], af[mi][2], af[mi][3],
                            aT + sw128(off));
                }
                uint32_t bf[2][4];
#pragma unroll
                for (int ni2 = 0; ni2 < 2; ni2++) {
                    uint32_t off = (uint32_t)(bRow + ni2 * 16) * 128 +
                                   (uint32_t)(bColH + ks * 16) * 2;
                    ldsm_x4(bf[ni2][0], bf[ni2][1], bf[ni2][2], bf[ni2][3],
                            bT + sw128(off));
                }
#pragma unroll
                for (int mi = 0; mi < 4; mi++) {
#pragma unroll
                    for (int ni = 0; ni < 4; ni++) {
                        uint32_t b0 = bf[ni >> 1][(ni & 1) * 2 + 0];
                        uint32_t b1 = bf[ni >> 1][(ni & 1) * 2 + 1];
                        mma16816(acc[mi][ni][0], acc[mi][ni][1],
                                 acc[mi][ni][2], acc[mi][ni][3],
                                 af[mi][0], af[mi][1], af[mi][2], af[mi][3],
                                 b0, b1);
                    }
                }
            }
        }
    }

    // ---------------- epilogue: out = acc + bias (no RMW) ----------------
    const int rowBase = blockIdx.y * 128 + warp_m * 64 + (lane >> 2);
    const int colBase = blockIdx.x * 128 + warp_n * 32 + (lane & 3) * 2;
#pragma unroll
    for (int mi = 0; mi < 4; mi++) {
#pragma unroll
        for (int ni = 0; ni < 4; ni++) {
            int r0 = rowBase + mi * 16;
            int c0 = colBase + ni * 8;
            float* o = out + (size_t)r0 * DOUT + c0;
            float b0 = __ldg(bias + c0);
            float b1 = __ldg(bias + c0 + 1);
            o[0] = acc[mi][ni][0] + b0;
            o[1] = acc[mi][ni][1] + b1;
            o += 8 * DOUT;
            o[0] = acc[mi][ni][2] + b0;
            o[1] = acc[mi][ni][3] + b1;
        }
    }
}

// ---------------------------------------------------------------------------
// Launcher
// ---------------------------------------------------------------------------
extern "C" void kernel_launch(void* const* d_in, const int* in_sizes, int n_in,
                              void* d_out, int out_size) {
    const float* x      = (const float*)d_in[0];
    const float* gate_w = (const float*)d_in[1];
    const float* base_w = (const float*)d_in[2];
    const float* base_b = (const float*)d_in[3];
    const float* lora_A = (const float*)d_in[4];
    const float* lora_B = (const float*)d_in[5];
    float* out = (float*)d_out;

    cudaFuncSetAttribute(k_low,
                         cudaFuncAttributeMaxDynamicSharedMemorySize, SMEM_TOTAL);
    cudaFuncSetAttribute(k_gemm1,
                         cudaFuncAttributeMaxDynamicSharedMemorySize, SMEM_TOTAL);

    // 1. prep: gate (+x conversion) | base_w/lora_A conversion | Bcat pack
    k_prep<<<PREP_GRID, 256>>>(x, gate_w, (const float4*)base_w,
                               (const float4*)lora_A, lora_B);

    // 2. low-rank activations, split-K partials
    k_low<<<dim3(NSPLIT, TOK / 128), 256, SMEM_TOTAL>>>();

    // 3. reduce partials, apply routing weights, emit fp16 z
    k_z<<<(TOK * JD / 2 + 255) / 256, 256>>>();

    // 4. fused: out = x@W^T + bias + z@Bcat^T
    k_gemm1<<<dim3(DOUT / 128, TOK / 128), 256, SMEM_TOTAL>>>(base_b, out);
}